// round 10
// baseline (speedup 1.0000x reference)
#include <cuda_runtime.h>
#include <cstdint>

// Problem dims
#define N_B   64
#define I_DIM 256
#define H_DIM 1024
#define O_DIM 18
#define T_DIM 500
#define PAIRS (N_B * T_DIM)          // 32000 (n,t) pairs

// Recurrence constants
#define D1 0.9048374180359595f       // exp(-1/10)
#define C1 0.2718281828459045f       // e/10
#define D2 0.36787944117144233f      // exp(-1)
#define C2 2.718281828459045f        // e
#define THETA 10.0f
#define REFSCALE -20.0f              // -scaleRef*theta

#define DUMMY_OFF (256 * 512)        // float2-row offset of the zero pad row

// ---- scratch (static device arrays; zero-initialized at load) ----
__device__ float g_W1p[(size_t)(I_DIM + 1) * H_DIM];   // paired cols [i][2c]=(c),(c+512); row 256 stays ZERO
__device__ float g_W2t[(size_t)H_DIM * O_DIM];         // W2 transposed [h][o]
__device__ unsigned int g_smask[(size_t)PAIRS * 32];   // s1 spike bitmask [m][h/32]
__device__ float g_y2[(size_t)PAIRS * O_DIM];          // layer-2 pre-psp
__device__ int g_listi[(size_t)PAIRS * 256];           // active idx*512 (float2 row offsets), padded to mult of 8
__device__ int g_counts[PAIRS];                        // padded counts

// ---------------------------------------------------------------------------
// Kernel 1: build per-(n,t) active-input lists, prescaled to float2-row
// offsets (i*512), padded to a multiple of 8 with the zero-row dummy.
// ---------------------------------------------------------------------------
__global__ void build_lists(const float* __restrict__ spike) {
    __shared__ float flags[I_DIM][32];
    int n  = blockIdx.x;
    int t0 = blockIdx.y * 32;
    int tid = threadIdx.x;
    int tl  = tid & 31;
    int io  = tid >> 5;

    #pragma unroll 4
    for (int ic = 0; ic < 32; ic++) {
        int i = ic * 8 + io;
        int t = t0 + tl;
        float v = 0.f;
        if (t < T_DIM) v = spike[((size_t)(n * I_DIM + i)) * T_DIM + t];
        flags[i][tl] = v;
    }
    __syncthreads();

    if (tid < 32) {
        int t = t0 + tid;
        if (t < T_DIM) {
            int m = n * T_DIM + t;
            int* lp = g_listi + (size_t)m * 256;
            int cnt = 0;
            for (int i = 0; i < I_DIM; i++) {
                if (flags[i][tid] != 0.f) lp[cnt++] = i << 9;   // i * 512
            }
            while (cnt & 7) lp[cnt++] = DUMMY_OFF;              // exact +0.0 padding
            g_counts[m] = cnt;
        }
    }
}

// ---------------------------------------------------------------------------
// Kernel 2: transpose W1 [H][I] -> paired layout g_W1p[i][2c,2c+1]=(W1t[i][c],W1t[i][c+512])
// ---------------------------------------------------------------------------
__global__ void transpose_w1(const float* __restrict__ W1) {
    __shared__ float tile[32][33];
    int i0 = blockIdx.x * 32;
    int h0 = blockIdx.y * 32;
    int tx = threadIdx.x, ty = threadIdx.y;   // (32, 8)
    #pragma unroll
    for (int r = 0; r < 32; r += 8)
        tile[ty + r][tx] = W1[(size_t)(h0 + ty + r) * I_DIM + i0 + tx];
    __syncthreads();
    #pragma unroll
    for (int r = 0; r < 32; r += 8) {
        int i = i0 + ty + r;
        int h = h0 + tx;
        int j = (h < 512) ? (2 * h) : (2 * (h - 512) + 1);
        g_W1p[(size_t)i * H_DIM + j] = tile[tx][ty + r];
    }
}

// ---------------------------------------------------------------------------
// Kernel 2b: transpose W2 [O][H] -> W2t [H][O]
// ---------------------------------------------------------------------------
__global__ void transpose_w2(const float* __restrict__ W2) {
    int idx = blockIdx.x * 256 + threadIdx.x;
    if (idx < O_DIM * H_DIM) {
        int o = idx / H_DIM;
        int h = idx - o * H_DIM;
        g_W2t[(size_t)h * O_DIM + o] = W2[idx];
    }
}

// ---------------------------------------------------------------------------
// Kernel 3: FUSED sparse GEMM1 + psp + spike scan (layer 1).
// Block = (n, 64-wide c-slice); thread owns h = c and h = c+512 (one float2
// load per active input). Iterates t sequentially; y1 never materialized.
// Inner loop: 8-deep load batches (MLP=8); list padded so batches are full.
// Emits s1 bitmask directly via warp ballots.
// ---------------------------------------------------------------------------
__global__ void __launch_bounds__(64) fused_l1() {
    int n = blockIdx.x;
    int c = blockIdx.y * 64 + threadIdx.x;            // 0..511
    int lane = threadIdx.x & 31;
    int word0 = c >> 5;                               // 0..15 (this warp's mask word)
    const float2* __restrict__ Wt2c = ((const float2*)g_W1p) + c;
    unsigned int* mp = g_smask + (size_t)n * T_DIM * 32;
    const int* __restrict__ lpbase = g_listi + (size_t)n * T_DIM * 256;
    const int* __restrict__ cntp   = g_counts + n * T_DIM;

    float p1a = 0.f, a1a = 0.f, p2a = 0.f, a2a = 0.f;   // h = c
    float p1b = 0.f, a1b = 0.f, p2b = 0.f, a2b = 0.f;   // h = c + 512

    for (int t = 0; t < T_DIM; t++) {
        int cnt = cntp[t];                             // multiple of 8
        const int* lp = lpbase + (size_t)t * 256;
        float acc0 = 0.f, acc1 = 0.f;

        for (int j = 0; j < cnt; j += 32) {
            int myoff = lp[j + lane];
            int lim = min(cnt - j, 32);                // multiple of 8
            for (int q = 0; q < lim; q += 8) {
                float2 w[8];
                #pragma unroll
                for (int r = 0; r < 8; r++) {
                    int off = __shfl_sync(0xffffffffu, myoff, q + r);
                    w[r] = Wt2c[off];
                }
                #pragma unroll
                for (int r = 0; r < 8; r++) { acc0 += w[r].x; acc1 += w[r].y; }
            }
        }

        // recurrence, h = c
        a1a = D1 * (a1a + p1a);
        p1a = D1 * p1a + acc0;
        a2a = D2 * (a2a + p2a);
        float ua = C1 * a1a + C2 * a2a;
        float sa = (ua - THETA >= 0.f) ? 1.0f : 0.0f;
        p2a = D2 * p2a + REFSCALE * sa;
        // recurrence, h = c + 512
        a1b = D1 * (a1b + p1b);
        p1b = D1 * p1b + acc1;
        a2b = D2 * (a2b + p2b);
        float ub = C1 * a1b + C2 * a2b;
        float sb = (ub - THETA >= 0.f) ? 1.0f : 0.0f;
        p2b = D2 * p2b + REFSCALE * sb;

        unsigned int b0 = __ballot_sync(0xffffffffu, sa != 0.f);
        unsigned int b1 = __ballot_sync(0xffffffffu, sb != 0.f);
        if (lane == 0) {
            mp[t * 32 + word0]      = b0;
            mp[t * 32 + 16 + word0] = b1;
        }
    }
}

// ---------------------------------------------------------------------------
// Kernel 4: bit-sparse GEMM2. Warp handles TWO m; merged bit loops overlap
// the two L1-hit load chains. Lanes 0..17 own output o.
// ---------------------------------------------------------------------------
__global__ void gemm2_sparse() {
    int warp = threadIdx.x >> 5;
    int lane = threadIdx.x & 31;
    int m = blockIdx.x * 16 + warp * 2;       // two m per warp

    unsigned int wA = g_smask[(size_t)m * 32 + lane];
    unsigned int wB = g_smask[(size_t)(m + 1) * 32 + lane];
    float accA = 0.f, accB = 0.f;
    bool act = (lane < O_DIM);

    #pragma unroll 4
    for (int src = 0; src < 32; src++) {
        unsigned int a = __shfl_sync(0xffffffffu, wA, src);
        unsigned int b = __shfl_sync(0xffffffffu, wB, src);
        int hb = src << 5;
        while (a | b) {
            if (a) {
                int bit = __ffs(a) - 1; a &= a - 1;
                if (act) accA += g_W2t[(size_t)(hb + bit) * O_DIM + lane];
            }
            if (b) {
                int bit = __ffs(b) - 1; b &= b - 1;
                if (act) accB += g_W2t[(size_t)(hb + bit) * O_DIM + lane];
            }
        }
    }
    if (act) {
        g_y2[(size_t)m * O_DIM + lane] = accA;
        g_y2[(size_t)(m + 1) * O_DIM + lane] = accB;
    }
}

// ---------------------------------------------------------------------------
// Kernel 5: fused psp + spike scan, layer 2. MLP=20. Out [n][o][t].
// ---------------------------------------------------------------------------
__global__ void scan_layer2(float* __restrict__ out) {
    int idx = blockIdx.x * blockDim.x + threadIdx.x;
    if (idx >= N_B * O_DIM) return;
    int n = idx / O_DIM;
    int o = idx - n * O_DIM;
    const float* __restrict__ yp = g_y2 + (size_t)n * T_DIM * O_DIM + o;
    float*       op = out + (size_t)idx * T_DIM;

    float p1 = 0.f, a1 = 0.f, p2 = 0.f, a2 = 0.f;
    for (int t = 0; t < T_DIM; t += 20) {
        float yy[20];
        #pragma unroll
        for (int k = 0; k < 20; k++)
            yy[k] = yp[(size_t)(t + k) * O_DIM];
        #pragma unroll
        for (int k = 0; k < 20; k++) {
            a1 = D1 * (a1 + p1);
            p1 = D1 * p1 + yy[k];
            a2 = D2 * (a2 + p2);
            float u = C1 * a1 + C2 * a2;
            float s = (u - THETA >= 0.f) ? 1.0f : 0.0f;
            p2 = D2 * p2 + REFSCALE * s;
            op[t + k] = s;
        }
    }
}

// ---------------------------------------------------------------------------
extern "C" void kernel_launch(void* const* d_in, const int* in_sizes, int n_in,
                              void* d_out, int out_size) {
    const float* spike = (const float*)d_in[0];   // [64][256][500]
    const float* W1    = (const float*)d_in[1];   // [1024][256]
    const float* W2    = (const float*)d_in[2];   // [18][1024]
    float* out = (float*)d_out;                   // [64][18][500]

    build_lists<<<dim3(N_B, 16), 256>>>(spike);
    transpose_w1<<<dim3(I_DIM / 32, H_DIM / 32), dim3(32, 8)>>>(W1);
    transpose_w2<<<(O_DIM * H_DIM + 255) / 256, 256>>>(W2);
    fused_l1<<<dim3(N_B, 8), 64>>>();
    gemm2_sparse<<<PAIRS / 16, 256>>>();
    scan_layer2<<<5, 256>>>(out);
}

// round 13
// speedup vs baseline: 3.0251x; 3.0251x over previous
#include <cuda_runtime.h>
#include <cstdint>

// Problem dims
#define N_B   64
#define I_DIM 256
#define H_DIM 1024
#define O_DIM 18
#define T_DIM 500
#define PAIRS (N_B * T_DIM)          // 32000 (n,t) pairs

// Recurrence constants
#define D1 0.9048374180359595f       // exp(-1/10)
#define C1 0.2718281828459045f       // e/10
#define D2 0.36787944117144233f      // exp(-1)
#define C2 2.718281828459045f        // e
#define THETA 10.0f
#define REFSCALE -20.0f              // -scaleRef*theta

#define DUMMY_OFF (I_DIM << 8)       // float4-row offset of appended zero row (row 256)

// ---- scratch (static device arrays; zero-initialized at module load) ----
__device__ float g_W1t[(size_t)(I_DIM + 1) * H_DIM];   // W1 transposed [i][h]; row 256 stays ZERO
__device__ float g_W2t[(size_t)H_DIM * O_DIM];         // W2 transposed [h][o]
__device__ float g_y1[(size_t)PAIRS * H_DIM];          // layer-1 pre-psp
__device__ unsigned int g_smask[(size_t)PAIRS * 32];   // s1 spike bitmask [m][h/32]
__device__ float g_y2[(size_t)PAIRS * O_DIM];          // layer-2 pre-psp
__device__ int g_listi[(size_t)PAIRS * 256];           // active idx<<8 (float4-row offsets), padded to mult of 8
__device__ int g_counts[PAIRS];                        // padded counts

// ---------------------------------------------------------------------------
// Kernel 1: build per-(n,t) active-input lists via warp-parallel ballots.
// Entry value = i << 8 (float4-row offset into W1t). Padded to multiple of 8
// with DUMMY_OFF (zero row -> exact +0.0 in the gather).
// ---------------------------------------------------------------------------
__global__ void build_lists(const float* __restrict__ spike) {
    __shared__ float flags[I_DIM][33];
    int n  = blockIdx.x;
    int t0 = blockIdx.y * 32;
    int tid = threadIdx.x;
    int tl  = tid & 31;
    int w   = tid >> 5;              // warp 0..7

    #pragma unroll 4
    for (int ic = 0; ic < 32; ic++) {
        int i = ic * 8 + w;
        int t = t0 + tl;
        float v = 0.f;
        if (t < T_DIM) v = spike[((size_t)(n * I_DIM + i)) * T_DIM + t];
        flags[i][tl] = v;
    }
    __syncthreads();

    // warp w emits lists for 4 t-values
    unsigned int ltmask = (1u << tl) - 1u;
    for (int tt = 0; tt < 4; tt++) {
        int tloc = w * 4 + tt;
        int t = t0 + tloc;
        if (t >= T_DIM) continue;
        int m = n * T_DIM + t;
        int* lp = g_listi + (size_t)m * 256;
        int base = 0;
        #pragma unroll
        for (int chunk = 0; chunk < 8; chunk++) {
            float v = flags[chunk * 32 + tl][tloc];
            unsigned int bal = __ballot_sync(0xffffffffu, v != 0.f);
            if (v != 0.f) lp[base + __popc(bal & ltmask)] = (chunk * 32 + tl) << 8;
            base += __popc(bal);
        }
        int padded = (base + 7) & ~7;
        if (tl < padded - base) lp[base + tl] = DUMMY_OFF;
        if (tl == 0) g_counts[m] = padded;
    }
}

// ---------------------------------------------------------------------------
// Kernel 2: transpose W1 [H][I] -> W1t [I][H] (row 256 left zero)
// ---------------------------------------------------------------------------
__global__ void transpose_w1(const float* __restrict__ W1) {
    __shared__ float tile[32][33];
    int i0 = blockIdx.x * 32;
    int h0 = blockIdx.y * 32;
    int tx = threadIdx.x, ty = threadIdx.y;   // (32, 8)
    #pragma unroll
    for (int r = 0; r < 32; r += 8)
        tile[ty + r][tx] = W1[(size_t)(h0 + ty + r) * I_DIM + i0 + tx];
    __syncthreads();
    #pragma unroll
    for (int r = 0; r < 32; r += 8)
        g_W1t[(size_t)(i0 + ty + r) * H_DIM + h0 + tx] = tile[tx][ty + r];
}

// ---------------------------------------------------------------------------
// Kernel 2b: transpose W2 [O][H] -> W2t [H][O]
// ---------------------------------------------------------------------------
__global__ void transpose_w2(const float* __restrict__ W2) {
    int idx = blockIdx.x * 256 + threadIdx.x;
    if (idx < O_DIM * H_DIM) {
        int o = idx / H_DIM;
        int h = idx - o * H_DIM;
        g_W2t[(size_t)h * O_DIM + o] = W2[idx];
    }
}

// ---------------------------------------------------------------------------
// Kernel 3: sparse GEMM1, float4 gathers, 8-deep load batches (no tail:
// lists padded with zero-row dummies -> exact +0.0). Warp per m, 32 lanes x
// float4 = 128 h. Addition order identical to element-sequential list order.
// ---------------------------------------------------------------------------
__global__ void gather_y1() {
    int warp = threadIdx.x >> 5;
    int lane = threadIdx.x & 31;
    int h4   = blockIdx.y * 32 + lane;        // float4 column index
    const float4* __restrict__ Wt = (const float4*)g_W1t;
    int m0 = blockIdx.x * 64;

    for (int k = 0; k < 8; k++) {
        int m = m0 + warp * 8 + k;
        int cnt = g_counts[m];                // multiple of 8
        const int* lp = g_listi + (size_t)m * 256;
        float4 acc = make_float4(0.f, 0.f, 0.f, 0.f);
        for (int j = 0; j < cnt; j += 8) {
            int4 u0 = *(const int4*)(lp + j);
            int4 u1 = *(const int4*)(lp + j + 4);
            float4 a0 = Wt[u0.x + h4];
            float4 a1 = Wt[u0.y + h4];
            float4 a2 = Wt[u0.z + h4];
            float4 a3 = Wt[u0.w + h4];
            float4 a4 = Wt[u1.x + h4];
            float4 a5 = Wt[u1.y + h4];
            float4 a6 = Wt[u1.z + h4];
            float4 a7 = Wt[u1.w + h4];
            acc.x += a0.x; acc.x += a1.x; acc.x += a2.x; acc.x += a3.x;
            acc.x += a4.x; acc.x += a5.x; acc.x += a6.x; acc.x += a7.x;
            acc.y += a0.y; acc.y += a1.y; acc.y += a2.y; acc.y += a3.y;
            acc.y += a4.y; acc.y += a5.y; acc.y += a6.y; acc.y += a7.y;
            acc.z += a0.z; acc.z += a1.z; acc.z += a2.z; acc.z += a3.z;
            acc.z += a4.z; acc.z += a5.z; acc.z += a6.z; acc.z += a7.z;
            acc.w += a0.w; acc.w += a1.w; acc.w += a2.w; acc.w += a3.w;
            acc.w += a4.w; acc.w += a5.w; acc.w += a6.w; acc.w += a7.w;
        }
        ((float4*)g_y1)[(size_t)m * (H_DIM / 4) + h4] = acc;
    }
}

// ---------------------------------------------------------------------------
// Kernel 4: fused psp + spike scan, layer 1. MLP=20. Emits s1 bitmask.
// ---------------------------------------------------------------------------
__global__ void scan_layer1() {
    int n = blockIdx.x >> 2;
    int h = ((blockIdx.x & 3) << 8) + threadIdx.x;
    int lane = threadIdx.x & 31;
    const float* __restrict__ yp = g_y1 + (size_t)n * T_DIM * H_DIM + h;
    unsigned int* mp = g_smask + (size_t)n * T_DIM * 32 + (h >> 5);

    float p1 = 0.f, a1 = 0.f, p2 = 0.f, a2 = 0.f;
    for (int t = 0; t < T_DIM; t += 20) {
        float yy[20];
        #pragma unroll
        for (int k = 0; k < 20; k++)
            yy[k] = yp[(size_t)(t + k) * H_DIM];
        #pragma unroll
        for (int k = 0; k < 20; k++) {
            a1 = D1 * (a1 + p1);
            p1 = D1 * p1 + yy[k];
            a2 = D2 * (a2 + p2);
            float u = C1 * a1 + C2 * a2;
            float s = (u - THETA >= 0.f) ? 1.0f : 0.0f;
            p2 = D2 * p2 + REFSCALE * s;
            unsigned int bal = __ballot_sync(0xffffffffu, s != 0.f);
            if (lane == 0) mp[(size_t)(t + k) * 32] = bal;
        }
    }
}

// ---------------------------------------------------------------------------
// Kernel 5: bit-sparse GEMM2. Warp handles TWO m; merged bit loops overlap
// the two L1-hit load chains. Lanes 0..17 own output o.
// ---------------------------------------------------------------------------
__global__ void gemm2_sparse() {
    int warp = threadIdx.x >> 5;
    int lane = threadIdx.x & 31;
    int m = blockIdx.x * 16 + warp * 2;       // two m per warp

    unsigned int wA = g_smask[(size_t)m * 32 + lane];
    unsigned int wB = g_smask[(size_t)(m + 1) * 32 + lane];
    float accA = 0.f, accB = 0.f;
    bool act = (lane < O_DIM);

    #pragma unroll 4
    for (int src = 0; src < 32; src++) {
        unsigned int a = __shfl_sync(0xffffffffu, wA, src);
        unsigned int b = __shfl_sync(0xffffffffu, wB, src);
        int hb = src << 5;
        while (a | b) {
            if (a) {
                int bit = __ffs(a) - 1; a &= a - 1;
                if (act) accA += g_W2t[(size_t)(hb + bit) * O_DIM + lane];
            }
            if (b) {
                int bit = __ffs(b) - 1; b &= b - 1;
                if (act) accB += g_W2t[(size_t)(hb + bit) * O_DIM + lane];
            }
        }
    }
    if (act) {
        g_y2[(size_t)m * O_DIM + lane] = accA;
        g_y2[(size_t)(m + 1) * O_DIM + lane] = accB;
    }
}

// ---------------------------------------------------------------------------
// Kernel 6: fused psp + spike scan, layer 2. MLP=20. Out [n][o][t].
// ---------------------------------------------------------------------------
__global__ void scan_layer2(float* __restrict__ out) {
    int idx = blockIdx.x * blockDim.x + threadIdx.x;
    if (idx >= N_B * O_DIM) return;
    int n = idx / O_DIM;
    int o = idx - n * O_DIM;
    const float* __restrict__ yp = g_y2 + (size_t)n * T_DIM * O_DIM + o;
    float*       op = out + (size_t)idx * T_DIM;

    float p1 = 0.f, a1 = 0.f, p2 = 0.f, a2 = 0.f;
    for (int t = 0; t < T_DIM; t += 20) {
        float yy[20];
        #pragma unroll
        for (int k = 0; k < 20; k++)
            yy[k] = yp[(size_t)(t + k) * O_DIM];
        #pragma unroll
        for (int k = 0; k < 20; k++) {
            a1 = D1 * (a1 + p1);
            p1 = D1 * p1 + yy[k];
            a2 = D2 * (a2 + p2);
            float u = C1 * a1 + C2 * a2;
            float s = (u - THETA >= 0.f) ? 1.0f : 0.0f;
            p2 = D2 * p2 + REFSCALE * s;
            op[t + k] = s;
        }
    }
}

// ---------------------------------------------------------------------------
extern "C" void kernel_launch(void* const* d_in, const int* in_sizes, int n_in,
                              void* d_out, int out_size) {
    const float* spike = (const float*)d_in[0];   // [64][256][500]
    const float* W1    = (const float*)d_in[1];   // [1024][256]
    const float* W2    = (const float*)d_in[2];   // [18][1024]
    float* out = (float*)d_out;                   // [64][18][500]

    build_lists<<<dim3(N_B, 16), 256>>>(spike);
    transpose_w1<<<dim3(I_DIM / 32, H_DIM / 32), dim3(32, 8)>>>(W1);
    transpose_w2<<<(O_DIM * H_DIM + 255) / 256, 256>>>(W2);
    gather_y1<<<dim3(500, 8), 256>>>();
    scan_layer1<<<256, 256>>>();
    gemm2_sparse<<<PAIRS / 16, 256>>>();
    scan_layer2<<<5, 256>>>(out);
}

// round 14
// speedup vs baseline: 3.1858x; 1.0531x over previous
#include <cuda_runtime.h>
#include <cstdint>

// Problem dims
#define N_B   64
#define I_DIM 256
#define H_DIM 1024
#define O_DIM 18
#define T_DIM 500
#define PAIRS (N_B * T_DIM)          // 32000 (n,t) pairs

// Recurrence constants
#define D1 0.9048374180359595f       // exp(-1/10)
#define C1 0.2718281828459045f       // e/10
#define D2 0.36787944117144233f      // exp(-1)
#define C2 2.718281828459045f        // e
#define THETA 10.0f
#define REFSCALE -20.0f              // -scaleRef*theta

// ---- scratch (static device arrays) ----
__device__ float g_W1t[(size_t)I_DIM * H_DIM];         // W1 transposed [i][h]
__device__ float g_W2t[(size_t)H_DIM * O_DIM];         // W2 transposed [h][o]
__device__ float g_y1[(size_t)PAIRS * H_DIM];          // layer-1 pre-psp
__device__ unsigned int g_smask[(size_t)PAIRS * 32];   // s1 spike bitmask [m][h/32]
__device__ float g_y2[(size_t)PAIRS * O_DIM];          // layer-2 pre-psp
__device__ int g_listi[(size_t)PAIRS * 256];           // active idx<<8 (float4-row offsets), EXACT count
__device__ int g_counts[PAIRS];

// ---------------------------------------------------------------------------
// Kernel 1: build per-(n,t) active-input lists via warp-parallel ballots.
// Entry value = i << 8 (float4-row offset into W1t). Exact counts, no padding.
// ---------------------------------------------------------------------------
__global__ void build_lists(const float* __restrict__ spike) {
    __shared__ float flags[I_DIM][33];
    int n  = blockIdx.x;
    int t0 = blockIdx.y * 32;
    int tid = threadIdx.x;
    int tl  = tid & 31;
    int w   = tid >> 5;              // warp 0..7

    #pragma unroll 4
    for (int ic = 0; ic < 32; ic++) {
        int i = ic * 8 + w;
        int t = t0 + tl;
        float v = 0.f;
        if (t < T_DIM) v = spike[((size_t)(n * I_DIM + i)) * T_DIM + t];
        flags[i][tl] = v;
    }
    __syncthreads();

    // warp w emits lists for 4 t-values
    unsigned int ltmask = (1u << tl) - 1u;
    for (int tt = 0; tt < 4; tt++) {
        int tloc = w * 4 + tt;
        int t = t0 + tloc;
        if (t >= T_DIM) continue;
        int m = n * T_DIM + t;
        int* lp = g_listi + (size_t)m * 256;
        int base = 0;
        #pragma unroll
        for (int chunk = 0; chunk < 8; chunk++) {
            float v = flags[chunk * 32 + tl][tloc];
            unsigned int bal = __ballot_sync(0xffffffffu, v != 0.f);
            if (v != 0.f) lp[base + __popc(bal & ltmask)] = (chunk * 32 + tl) << 8;
            base += __popc(bal);
        }
        if (tl == 0) g_counts[m] = base;
    }
}

// ---------------------------------------------------------------------------
// Kernel 2: transpose W1 [H][I] -> W1t [I][H]; extra blocks handle W2 -> W2t.
// ---------------------------------------------------------------------------
__global__ void transpose_w(const float* __restrict__ W1,
                            const float* __restrict__ W2) {
    if (blockIdx.y < H_DIM / 32) {
        __shared__ float tile[32][33];
        int i0 = blockIdx.x * 32;
        int h0 = blockIdx.y * 32;
        int tx = threadIdx.x, ty = threadIdx.y;   // (32, 8)
        #pragma unroll
        for (int r = 0; r < 32; r += 8)
            tile[ty + r][tx] = W1[(size_t)(h0 + ty + r) * I_DIM + i0 + tx];
        __syncthreads();
        #pragma unroll
        for (int r = 0; r < 32; r += 8)
            g_W1t[(size_t)(i0 + ty + r) * H_DIM + h0 + tx] = tile[tx][ty + r];
    } else {
        int idx = (blockIdx.x + (blockIdx.y - H_DIM / 32) * gridDim.x) * 256
                  + threadIdx.y * 32 + threadIdx.x;
        if (idx < O_DIM * H_DIM) {
            int o = idx / H_DIM;
            int h = idx - o * H_DIM;
            g_W2t[(size_t)h * O_DIM + o] = W2[idx];
        }
    }
}

// ---------------------------------------------------------------------------
// Kernel 3: sparse GEMM1, float4 gathers, prescaled int offsets (IADD+LDG
// addressing), MLP=4 batches + scalar tail, NO padding. Warp per m,
// 32 lanes x float4 = 128 h.
// ---------------------------------------------------------------------------
__global__ void gather_y1() {
    int warp = threadIdx.x >> 5;
    int lane = threadIdx.x & 31;
    int h4   = blockIdx.y * 32 + lane;        // float4 column index
    const float4* __restrict__ Wt = (const float4*)g_W1t;
    int m0 = blockIdx.x * 64;

    for (int k = 0; k < 8; k++) {
        int m = m0 + warp * 8 + k;
        int cnt = g_counts[m];
        const int* lp = g_listi + (size_t)m * 256;
        float4 acc = make_float4(0.f, 0.f, 0.f, 0.f);
        int j = 0;
        for (; j + 4 <= cnt; j += 4) {
            int4 u = *(const int4*)(lp + j);
            float4 a = Wt[u.x + h4];
            float4 b = Wt[u.y + h4];
            float4 c = Wt[u.z + h4];
            float4 d = Wt[u.w + h4];
            acc.x += a.x; acc.x += b.x; acc.x += c.x; acc.x += d.x;
            acc.y += a.y; acc.y += b.y; acc.y += c.y; acc.y += d.y;
            acc.z += a.z; acc.z += b.z; acc.z += c.z; acc.z += d.z;
            acc.w += a.w; acc.w += b.w; acc.w += c.w; acc.w += d.w;
        }
        for (; j < cnt; j++) {
            float4 a = Wt[lp[j] + h4];
            acc.x += a.x; acc.y += a.y; acc.z += a.z; acc.w += a.w;
        }
        ((float4*)g_y1)[(size_t)m * (H_DIM / 4) + h4] = acc;
    }
}

// ---------------------------------------------------------------------------
// Kernel 4: fused psp + spike scan, layer 1. MLP=20. Emits s1 bitmask.
// ---------------------------------------------------------------------------
__global__ void scan_layer1() {
    int n = blockIdx.x >> 2;
    int h = ((blockIdx.x & 3) << 8) + threadIdx.x;
    int lane = threadIdx.x & 31;
    const float* __restrict__ yp = g_y1 + (size_t)n * T_DIM * H_DIM + h;
    unsigned int* mp = g_smask + (size_t)n * T_DIM * 32 + (h >> 5);

    float p1 = 0.f, a1 = 0.f, p2 = 0.f, a2 = 0.f;
    for (int t = 0; t < T_DIM; t += 20) {
        float yy[20];
        #pragma unroll
        for (int k = 0; k < 20; k++)
            yy[k] = yp[(size_t)(t + k) * H_DIM];
        #pragma unroll
        for (int k = 0; k < 20; k++) {
            a1 = D1 * (a1 + p1);
            p1 = D1 * p1 + yy[k];
            a2 = D2 * (a2 + p2);
            float u = C1 * a1 + C2 * a2;
            float s = (u - THETA >= 0.f) ? 1.0f : 0.0f;
            p2 = D2 * p2 + REFSCALE * s;
            unsigned int bal = __ballot_sync(0xffffffffu, s != 0.f);
            if (lane == 0) mp[(size_t)(t + k) * 32] = bal;
        }
    }
}

// ---------------------------------------------------------------------------
// Kernel 5: bit-sparse GEMM2. Warp handles TWO m; merged bit loops overlap
// the two L1-hit load chains. Lanes 0..17 own output o.
// ---------------------------------------------------------------------------
__global__ void gemm2_sparse() {
    int warp = threadIdx.x >> 5;
    int lane = threadIdx.x & 31;
    int m = blockIdx.x * 16 + warp * 2;       // two m per warp

    unsigned int wA = g_smask[(size_t)m * 32 + lane];
    unsigned int wB = g_smask[(size_t)(m + 1) * 32 + lane];
    float accA = 0.f, accB = 0.f;
    bool act = (lane < O_DIM);

    #pragma unroll 4
    for (int src = 0; src < 32; src++) {
        unsigned int a = __shfl_sync(0xffffffffu, wA, src);
        unsigned int b = __shfl_sync(0xffffffffu, wB, src);
        int hb = src << 5;
        while (a | b) {
            if (a) {
                int bit = __ffs(a) - 1; a &= a - 1;
                if (act) accA += g_W2t[(size_t)(hb + bit) * O_DIM + lane];
            }
            if (b) {
                int bit = __ffs(b) - 1; b &= b - 1;
                if (act) accB += g_W2t[(size_t)(hb + bit) * O_DIM + lane];
            }
        }
    }
    if (act) {
        g_y2[(size_t)m * O_DIM + lane] = accA;
        g_y2[(size_t)(m + 1) * O_DIM + lane] = accB;
    }
}

// ---------------------------------------------------------------------------
// Kernel 6: fused psp + spike scan, layer 2. MLP=20. Out [n][o][t].
// ---------------------------------------------------------------------------
__global__ void scan_layer2(float* __restrict__ out) {
    int idx = blockIdx.x * blockDim.x + threadIdx.x;
    if (idx >= N_B * O_DIM) return;
    int n = idx / O_DIM;
    int o = idx - n * O_DIM;
    const float* __restrict__ yp = g_y2 + (size_t)n * T_DIM * O_DIM + o;
    float*       op = out + (size_t)idx * T_DIM;

    float p1 = 0.f, a1 = 0.f, p2 = 0.f, a2 = 0.f;
    for (int t = 0; t < T_DIM; t += 20) {
        float yy[20];
        #pragma unroll
        for (int k = 0; k < 20; k++)
            yy[k] = yp[(size_t)(t + k) * O_DIM];
        #pragma unroll
        for (int k = 0; k < 20; k++) {
            a1 = D1 * (a1 + p1);
            p1 = D1 * p1 + yy[k];
            a2 = D2 * (a2 + p2);
            float u = C1 * a1 + C2 * a2;
            float s = (u - THETA >= 0.f) ? 1.0f : 0.0f;
            p2 = D2 * p2 + REFSCALE * s;
            op[t + k] = s;
        }
    }
}

// ---------------------------------------------------------------------------
extern "C" void kernel_launch(void* const* d_in, const int* in_sizes, int n_in,
                              void* d_out, int out_size) {
    const float* spike = (const float*)d_in[0];   // [64][256][500]
    const float* W1    = (const float*)d_in[1];   // [1024][256]
    const float* W2    = (const float*)d_in[2];   // [18][1024]
    float* out = (float*)d_out;                   // [64][18][500]

    build_lists<<<dim3(N_B, 16), 256>>>(spike);
    // W1 transpose uses y-blocks [0, 32); y-blocks [32, 32+9) cover W2 (8x256=2048 <= needed 18432/256=72... use 9 extra y per x=8 -> 8*9*256=18432)
    transpose_w<<<dim3(I_DIM / 32, H_DIM / 32 + 9), dim3(32, 8)>>>(W1, W2);
    gather_y1<<<dim3(500, 8), 256>>>();
    scan_layer1<<<256, 256>>>();
    gemm2_sparse<<<PAIRS / 16, 256>>>();
    scan_layer2<<<5, 256>>>(out);
}